// round 7
// baseline (speedup 1.0000x reference)
#include <cuda_runtime.h>
#include <math.h>
#include <stdint.h>

#define BTOT 8192      // B*T rows
#define CDIM 2048      // channels
#define TSEQ 2048      // sequence length
#define NHEAD 16
#define HDIM 128

// -------- scratch (device globals; allocation-free) --------
__device__ float g_nx [BTOT * CDIM];
__device__ float g_q  [BTOT * CDIM];
__device__ float g_k  [BTOT * CDIM];
__device__ float g_v  [BTOT * CDIM];
__device__ float g_att[BTOT * CDIM];

__device__ __forceinline__ float to_tf32(float x) {
    uint32_t u;
    asm("cvt.rna.tf32.f32 %0, %1;" : "=r"(u) : "f"(x));
    return __uint_as_float(u);
}
__device__ __forceinline__ float4 tf32x4(float4 v) {
    return make_float4(to_tf32(v.x), to_tf32(v.y), to_tf32(v.z), to_tf32(v.w));
}

// ===================== LayerNorm (output pre-rounded to tf32) =====================
__global__ __launch_bounds__(256) void ln_kernel(const float* __restrict__ x,
                                                 const float* __restrict__ gamma,
                                                 const float* __restrict__ beta) {
    int row = blockIdx.x;
    int tid = threadIdx.x;
    const float* px = x + row * CDIM;

    float4 a0 = *(const float4*)(px + tid * 4);
    float4 a1 = *(const float4*)(px + 1024 + tid * 4);

    float s = a0.x + a0.y + a0.z + a0.w + a1.x + a1.y + a1.z + a1.w;
    float q = a0.x*a0.x + a0.y*a0.y + a0.z*a0.z + a0.w*a0.w
            + a1.x*a1.x + a1.y*a1.y + a1.z*a1.z + a1.w*a1.w;

    #pragma unroll
    for (int off = 16; off; off >>= 1) {
        s += __shfl_xor_sync(0xffffffffu, s, off);
        q += __shfl_xor_sync(0xffffffffu, q, off);
    }
    __shared__ float sh[16];
    if ((tid & 31) == 0) { sh[tid >> 5] = s; sh[8 + (tid >> 5)] = q; }
    __syncthreads();
    float ts = 0.f, tq = 0.f;
    #pragma unroll
    for (int i = 0; i < 8; i++) { ts += sh[i]; tq += sh[8 + i]; }

    float mu   = ts * (1.f / 2048.f);
    float var  = tq * (1.f / 2048.f) - mu * mu;
    float rstd = rsqrtf(var + 1e-5f);

    float4 g0 = *(const float4*)(gamma + tid * 4);
    float4 g1 = *(const float4*)(gamma + 1024 + tid * 4);
    float4 b0 = *(const float4*)(beta + tid * 4);
    float4 b1 = *(const float4*)(beta + 1024 + tid * 4);

    float* po = g_nx + row * CDIM;
    float4 o0, o1;
    o0.x = (a0.x - mu) * rstd * g0.x + b0.x;
    o0.y = (a0.y - mu) * rstd * g0.y + b0.y;
    o0.z = (a0.z - mu) * rstd * g0.z + b0.z;
    o0.w = (a0.w - mu) * rstd * g0.w + b0.w;
    o1.x = (a1.x - mu) * rstd * g1.x + b1.x;
    o1.y = (a1.y - mu) * rstd * g1.y + b1.y;
    o1.z = (a1.z - mu) * rstd * g1.z + b1.z;
    o1.w = (a1.w - mu) * rstd * g1.w + b1.w;
    *(float4*)(po + tid * 4)        = tf32x4(o0);   // pre-round for tf32 GEMM A-operand
    *(float4*)(po + 1024 + tid * 4) = tf32x4(o1);
}

// ===================== tf32 tensor-core GEMM v2 =====================
// Y = A[M,2048] * W[2048,2048] + bias (+ residual). 128x128 tile, BK=32,
// 256 thr (8 warps 2x4, warp tile 64x32). Double-buffered smem, ONE barrier
// per K-iter. A stored k-PERMUTED: As[m][8*(k&3)+(k>>2)], stride 36 -> each
// kc-pair's A fragment is one conflict-free LDS.128. B natural [k][n] stride 136.
// grid.z selects among 3 (W, bias, Y) sets for fused QKV.
#define TG2_SMEM ((2*128*36 + 2*32*136) * 4)   // 71680 B

template<int MODE, int CVTA>   // MODE1: +residual ; CVTA1: cvt A at staging
__global__ __launch_bounds__(256, 2) void tg2_kernel(
    const float* __restrict__ A,
    const float* __restrict__ W0, const float* __restrict__ W1, const float* __restrict__ W2,
    const float* __restrict__ c0, const float* __restrict__ c1, const float* __restrict__ c2,
    const float* __restrict__ R,
    float* __restrict__ Y0, float* __restrict__ Y1, float* __restrict__ Y2)
{
    const int K = CDIM, N = CDIM;
    extern __shared__ float smp[];
    float* Asm = smp;                 // [2][128][36]
    float* Bsm = smp + 2 * 128 * 36;  // [2][32][136]

    int z = blockIdx.z;
    const float* W    = (z == 0) ? W0 : (z == 1) ? W1 : W2;
    const float* bias = (z == 0) ? c0 : (z == 1) ? c1 : c2;
    float*       Y    = (z == 0) ? Y0 : (z == 1) ? Y1 : Y2;

    int tid = threadIdx.x, lane = tid & 31, warp = tid >> 5;
    int bm = blockIdx.y * 128, bn = blockIdx.x * 128;

    // A staging map: warp covers 4 rows stride 2 (bank-conflict-free perm stores)
    int mloc = (warp & 1) + 8 * (warp >> 1) + 2 * (lane >> 3);   // 0..31 (+32*it)
    int ac   = lane & 7;                                         // k-chunk
    const float* Ap = A + (size_t)(bm + mloc) * K + 4 * ac;

    // B staging map (unchanged, float4 stores)
    int ldr = tid >> 3;            // k-row 0..31
    int ldc = (tid & 7) * 4;       // n-chunk
    const float* Bp = W + (size_t)ldr * N + bn + ldc;

    float c[4][4][4];
    #pragma unroll
    for (int mi = 0; mi < 4; mi++)
        #pragma unroll
        for (int ni = 0; ni < 4; ni++)
            #pragma unroll
            for (int r = 0; r < 4; r++) c[mi][ni][r] = 0.f;

    int wm = warp >> 2, wn = warp & 3;
    int mbase = wm * 64, nbase = wn * 32;
    int lq = lane >> 2, lr = lane & 3;

    float4 pa[4], pb[4];

    // ---- prologue: stage k-iter 0 into buffer 0 ----
    #pragma unroll
    for (int it = 0; it < 4; it++) {
        pa[it] = *(const float4*)(Ap + (size_t)(it * 32) * K);
        pb[it] = *(const float4*)(Bp + it * 32);
    }
    #pragma unroll
    for (int it = 0; it < 4; it++) {
        float4 v = CVTA ? tf32x4(pa[it]) : pa[it];
        float* as = Asm + (mloc + 32 * it) * 36 + ac;
        as[0] = v.x; as[8] = v.y; as[16] = v.z; as[24] = v.w;
        *(float4*)(Bsm + ldr * 136 + ldc + 32 * it) = tf32x4(pb[it]);
    }
    __syncthreads();

    const int NITER = K / 32;   // 64
    for (int i = 0; i < NITER; ++i) {
        int p = i & 1;
        const float* Ab = Asm + p * 4608;
        const float* Bb = Bsm + p * 4352;

        if (i + 1 < NITER) {   // prefetch next tile (latency hidden by MMAs)
            int kn = (i + 1) * 32;
            #pragma unroll
            for (int it = 0; it < 4; it++) {
                pa[it] = *(const float4*)(Ap + (size_t)(it * 32) * K + kn);
                pb[it] = *(const float4*)(Bp + (size_t)kn * N + it * 32);
            }
        }

        // ---- compute from buf[p] ----
        #pragma unroll
        for (int pp = 0; pp < 2; pp++) {            // kc-pairs {0,1},{2,3}
            float bb[2][4][2];
            #pragma unroll
            for (int h = 0; h < 2; h++) {
                int kk = (2 * pp + h) * 8;
                #pragma unroll
                for (int ni = 0; ni < 4; ni++) {
                    int nc = nbase + ni * 8 + lq;
                    bb[h][ni][0] = Bb[(kk + lr) * 136 + nc];
                    bb[h][ni][1] = Bb[(kk + lr + 4) * 136 + nc];
                }
            }
            #pragma unroll
            for (int mi = 0; mi < 4; mi++) {
                int r0 = mbase + mi * 16 + lq;
                float4 qa0 = *(const float4*)(Ab + r0 * 36 + 8 * lr + 4 * pp);
                float4 qa1 = *(const float4*)(Ab + (r0 + 8) * 36 + 8 * lr + 4 * pp);
                #pragma unroll
                for (int ni = 0; ni < 4; ni++)
                    asm volatile(
                        "mma.sync.aligned.m16n8k8.row.col.f32.tf32.tf32.f32 "
                        "{%0,%1,%2,%3}, {%4,%5,%6,%7}, {%8,%9}, {%0,%1,%2,%3};"
                        : "+f"(c[mi][ni][0]), "+f"(c[mi][ni][1]),
                          "+f"(c[mi][ni][2]), "+f"(c[mi][ni][3])
                        : "r"(__float_as_uint(qa0.x)), "r"(__float_as_uint(qa1.x)),
                          "r"(__float_as_uint(qa0.y)), "r"(__float_as_uint(qa1.y)),
                          "r"(__float_as_uint(bb[0][ni][0])), "r"(__float_as_uint(bb[0][ni][1])));
                #pragma unroll
                for (int ni = 0; ni < 4; ni++)
                    asm volatile(
                        "mma.sync.aligned.m16n8k8.row.col.f32.tf32.tf32.f32 "
                        "{%0,%1,%2,%3}, {%4,%5,%6,%7}, {%8,%9}, {%0,%1,%2,%3};"
                        : "+f"(c[mi][ni][0]), "+f"(c[mi][ni][1]),
                          "+f"(c[mi][ni][2]), "+f"(c[mi][ni][3])
                        : "r"(__float_as_uint(qa0.z)), "r"(__float_as_uint(qa1.z)),
                          "r"(__float_as_uint(qa0.w)), "r"(__float_as_uint(qa1.w)),
                          "r"(__float_as_uint(bb[1][ni][0])), "r"(__float_as_uint(bb[1][ni][1])));
            }
        }

        // ---- stage next tile into buf[1-p] (readers finished before last sync) ----
        if (i + 1 < NITER) {
            float* An = Asm + (1 - p) * 4608;
            float* Bn = Bsm + (1 - p) * 4352;
            #pragma unroll
            for (int it = 0; it < 4; it++) {
                float4 v = CVTA ? tf32x4(pa[it]) : pa[it];
                float* as = An + (mloc + 32 * it) * 36 + ac;
                as[0] = v.x; as[8] = v.y; as[16] = v.z; as[24] = v.w;
                *(float4*)(Bn + ldr * 136 + ldc + 32 * it) = tf32x4(pb[it]);
            }
        }
        __syncthreads();
    }

    // ---- epilogue: bias (+residual) ----
    #pragma unroll
    for (int mi = 0; mi < 4; mi++) {
        int r0 = bm + mbase + mi * 16 + lq;
        #pragma unroll
        for (int ni = 0; ni < 4; ni++) {
            int cb = bn + nbase + ni * 8 + 2 * lr;
            float bx = bias[cb], by = bias[cb + 1];
            float2 v0 = make_float2(c[mi][ni][0] + bx, c[mi][ni][1] + by);
            float2 v1 = make_float2(c[mi][ni][2] + bx, c[mi][ni][3] + by);
            if (MODE == 1) {
                float2 r0v = *(const float2*)(R + (size_t)r0 * N + cb);
                float2 r1v = *(const float2*)(R + (size_t)(r0 + 8) * N + cb);
                v0.x += r0v.x; v0.y += r0v.y;
                v1.x += r1v.x; v1.y += r1v.y;
            }
            *(float2*)(Y + (size_t)r0 * N + cb)       = v0;
            *(float2*)(Y + (size_t)(r0 + 8) * N + cb) = v1;
        }
    }
}

// ===================== RoPE (in-place on g_q / g_k) =====================
__global__ __launch_bounds__(256) void rope_kernel() {
    int row = blockIdx.x;
    float* buf = (blockIdx.y == 0) ? g_q : g_k;
    int t = row & (TSEQ - 1);

    __shared__ float cs[64], sn[64];
    if (threadIdx.x < 64) {
        float inv = powf(10000.f, -(float)threadIdx.x / 64.f);
        float ang = (float)t * inv;
        cs[threadIdx.x] = cosf(ang);
        sn[threadIdx.x] = sinf(ang);
    }
    __syncthreads();

    float* p = buf + (size_t)row * CDIM;
    for (int idx = threadIdx.x; idx < NHEAD * 64; idx += 256) {
        int h = idx >> 6, f = idx & 63;
        float a = p[h * 128 + f];
        float b = p[h * 128 + 64 + f];
        p[h * 128 + f]      = a * cs[f] - b * sn[f];
        p[h * 128 + 64 + f] = b * cs[f] + a * sn[f];
    }
}

// ===================== Flash attention (tf32 tensor cores, causal) =====================
#define FLASH2_SMEM ((128*132 + 64*132 + 64*136 + 128*68) * 4)   // 171008 B

__global__ __launch_bounds__(256, 1) void flash_tc_kernel() {
    extern __shared__ float sm[];
    float* Qs = sm;                    // [128][132]
    float* Ks = Qs + 128 * 132;        // [64][132]
    float* Vs = Ks + 64 * 132;         // [64][136]
    float* Ps = Vs + 64 * 136;         // [128][68]

    int qb = gridDim.x - 1 - blockIdx.x;
    int h = blockIdx.y, b = blockIdx.z;
    int tid = threadIdx.x, lane = tid & 31, warp = tid >> 5;
    int lq = lane >> 2, lr = lane & 3;

    size_t base = ((size_t)b * TSEQ) * CDIM + (size_t)h * HDIM;

    #pragma unroll
    for (int it = 0; it < 16; it++) {
        int f4 = tid + it * 256;
        int r  = f4 >> 5;
        int c4 = (f4 & 31) * 4;
        float4 v = *(const float4*)(g_q + base + (size_t)(qb * 128 + r) * CDIM + c4);
        *(float4*)&Qs[r * 132 + c4] = tf32x4(v);
    }

    float m0 = -1e30f, m1 = -1e30f, l0 = 0.f, l1 = 0.f;
    float O[16][4];
    #pragma unroll
    for (int nt = 0; nt < 16; nt++)
        #pragma unroll
        for (int r = 0; r < 4; r++) O[nt][r] = 0.f;

    const float scale = 0.08838834764831845f;
    int arow = warp * 16 + lq;
    int prow0 = arow * 68, prow1 = (arow + 8) * 68;
    int grow0 = qb * 128 + arow;

    int nkb = 2 * (qb + 1);
    for (int kb = 0; kb < nkb; kb++) {
        __syncthreads();

        #pragma unroll
        for (int it = 0; it < 8; it++) {
            int f4 = tid + it * 256;
            int r  = f4 >> 5;
            int c4 = (f4 & 31) * 4;
            size_t g = base + (size_t)(kb * 64 + r) * CDIM + c4;
            *(float4*)&Ks[r * 132 + c4] = tf32x4(*(const float4*)(g_k + g));
            *(float4*)&Vs[r * 136 + c4] = tf32x4(*(const float4*)(g_v + g));
        }
        __syncthreads();

        float s[8][4];
        #pragma unroll
        for (int nt = 0; nt < 8; nt++)
            #pragma unroll
            for (int r = 0; r < 4; r++) s[nt][r] = 0.f;

        #pragma unroll
        for (int kt = 0; kt < 16; kt++) {
            int kk = kt * 8;
            uint32_t a0 = __float_as_uint(Qs[arow * 132 + kk + lr]);
            uint32_t a1 = __float_as_uint(Qs[(arow + 8) * 132 + kk + lr]);
            uint32_t a2 = __float_as_uint(Qs[arow * 132 + kk + lr + 4]);
            uint32_t a3 = __float_as_uint(Qs[(arow + 8) * 132 + kk + lr + 4]);
            #pragma unroll
            for (int nt = 0; nt < 8; nt++) {
                int nc = nt * 8 + lq;
                uint32_t b0 = __float_as_uint(Ks[nc * 132 + kk + lr]);
                uint32_t b1 = __float_as_uint(Ks[nc * 132 + kk + lr + 4]);
                asm volatile(
                    "mma.sync.aligned.m16n8k8.row.col.f32.tf32.tf32.f32 "
                    "{%0,%1,%2,%3}, {%4,%5,%6,%7}, {%8,%9}, {%0,%1,%2,%3};"
                    : "+f"(s[nt][0]), "+f"(s[nt][1]), "+f"(s[nt][2]), "+f"(s[nt][3])
                    : "r"(a0), "r"(a1), "r"(a2), "r"(a3), "r"(b0), "r"(b1));
            }
        }

        bool needmask = (kb * 64 + 63 > qb * 128 + warp * 16);
        float t0 = -1e30f, t1 = -1e30f;
        #pragma unroll
        for (int nt = 0; nt < 8; nt++) {
            if (needmask) {
                int c0 = kb * 64 + nt * 8 + 2 * lr;
                s[nt][0] = (c0     <= grow0)     ? s[nt][0] * scale : -1e30f;
                s[nt][1] = (c0 + 1 <= grow0)     ? s[nt][1] * scale : -1e30f;
                s[nt][2] = (c0     <= grow0 + 8) ? s[nt][2] * scale : -1e30f;
                s[nt][3] = (c0 + 1 <= grow0 + 8) ? s[nt][3] * scale : -1e30f;
            } else {
                s[nt][0] *= scale; s[nt][1] *= scale;
                s[nt][2] *= scale; s[nt][3] *= scale;
            }
            t0 = fmaxf(t0, fmaxf(s[nt][0], s[nt][1]));
            t1 = fmaxf(t1, fmaxf(s[nt][2], s[nt][3]));
        }
        t0 = fmaxf(t0, __shfl_xor_sync(0xffffffffu, t0, 1));
        t0 = fmaxf(t0, __shfl_xor_sync(0xffffffffu, t0, 2));
        t1 = fmaxf(t1, __shfl_xor_sync(0xffffffffu, t1, 1));
        t1 = fmaxf(t1, __shfl_xor_sync(0xffffffffu, t1, 2));

        float mn0 = fmaxf(m0, t0), mn1 = fmaxf(m1, t1);
        float al0 = __expf(m0 - mn0), al1 = __expf(m1 - mn1);
        float rs0 = 0.f, rs1 = 0.f;
        #pragma unroll
        for (int nt = 0; nt < 8; nt++) {
            float p00 = to_tf32(__expf(s[nt][0] - mn0));
            float p01 = to_tf32(__expf(s[nt][1] - mn0));
            float p10 = to_tf32(__expf(s[nt][2] - mn1));
            float p11 = to_tf32(__expf(s[nt][3] - mn1));
            rs0 += p00 + p01;
            rs1 += p10 + p11;
            *(float2*)&Ps[prow0 + nt * 8 + 2 * lr] = make_float2(p00, p01);
            *(float2*)&Ps[prow1 + nt * 8 + 2 * lr] = make_float2(p10, p11);
        }
        rs0 += __shfl_xor_sync(0xffffffffu, rs0, 1);
        rs0 += __shfl_xor_sync(0xffffffffu, rs0, 2);
        rs1 += __shfl_xor_sync(0xffffffffu, rs1, 1);
        rs1 += __shfl_xor_sync(0xffffffffu, rs1, 2);

        l0 = l0 * al0 + rs0;  l1 = l1 * al1 + rs1;
        m0 = mn0;             m1 = mn1;
        #pragma unroll
        for (int nt = 0; nt < 16; nt++) {
            O[nt][0] *= al0; O[nt][1] *= al0;
            O[nt][2] *= al1; O[nt][3] *= al1;
        }
        __syncwarp();

        #pragma unroll
        for (int kt = 0; kt < 8; kt++) {
            int kk = kt * 8;
            uint32_t a0 = __float_as_uint(Ps[prow0 + kk + lr]);
            uint32_t a1 = __float_as_uint(Ps[prow1 + kk + lr]);
            uint32_t a2 = __float_as_uint(Ps[prow0 + kk + lr + 4]);
            uint32_t a3 = __float_as_uint(Ps[prow1 + kk + lr + 4]);
            #pragma unroll
            for (int nt = 0; nt < 16; nt++) {
                int nc = nt * 8 + lq;
                uint32_t b0 = __float_as_uint(Vs[(kk + lr) * 136 + nc]);
                uint32_t b1 = __float_as_uint(Vs[(kk + lr + 4) * 136 + nc]);
                asm volatile(
                    "mma.sync.aligned.m16n8k8.row.col.f32.tf32.tf32.f32 "
                    "{%0,%1,%2,%3}, {%4,%5,%6,%7}, {%8,%9}, {%0,%1,%2,%3};"
                    : "+f"(O[nt][0]), "+f"(O[nt][1]), "+f"(O[nt][2]), "+f"(O[nt][3])
                    : "r"(a0), "r"(a1), "r"(a2), "r"(a3), "r"(b0), "r"(b1));
            }
        }
    }

    float inv0 = 1.f / l0, inv1 = 1.f / l1;
    #pragma unroll
    for (int nt = 0; nt < 16; nt++) {
        int c = nt * 8 + 2 * lr;
        *(float2*)(g_att + base + (size_t)grow0 * CDIM + c) =
            make_float2(O[nt][0] * inv0, O[nt][1] * inv0);
        *(float2*)(g_att + base + (size_t)(grow0 + 8) * CDIM + c) =
            make_float2(O[nt][2] * inv1, O[nt][3] * inv1);
    }
}

// ===================== launch =====================
extern "C" void kernel_launch(void* const* d_in, const int* in_sizes, int n_in,
                              void* d_out, int out_size) {
    const float* x    = (const float*)d_in[0];
    const float* ln_g = (const float*)d_in[1];
    const float* ln_b = (const float*)d_in[2];
    const float* Wq   = (const float*)d_in[3];
    const float* bq   = (const float*)d_in[4];
    const float* Wk   = (const float*)d_in[5];
    const float* bk   = (const float*)d_in[6];
    const float* Wv   = (const float*)d_in[7];
    const float* bv   = (const float*)d_in[8];
    const float* Wo   = (const float*)d_in[9];
    const float* bo   = (const float*)d_in[10];
    float* out = (float*)d_out;

    float *nx, *qp, *kp, *vp, *ap;
    cudaGetSymbolAddress((void**)&nx, g_nx);
    cudaGetSymbolAddress((void**)&qp, g_q);
    cudaGetSymbolAddress((void**)&kp, g_k);
    cudaGetSymbolAddress((void**)&vp, g_v);
    cudaGetSymbolAddress((void**)&ap, g_att);

    cudaFuncSetAttribute(flash_tc_kernel, cudaFuncAttributeMaxDynamicSharedMemorySize, FLASH2_SMEM);
    cudaFuncSetAttribute(tg2_kernel<0,0>, cudaFuncAttributeMaxDynamicSharedMemorySize, TG2_SMEM);
    cudaFuncSetAttribute(tg2_kernel<1,1>, cudaFuncAttributeMaxDynamicSharedMemorySize, TG2_SMEM);

    ln_kernel<<<BTOT, 256>>>(x, ln_g, ln_b);

    // fused Q/K/V projections (grid.z selects weight set)
    tg2_kernel<0,0><<<dim3(16, 64, 3), 256, TG2_SMEM>>>(
        nx, Wq, Wk, Wv, bq, bk, bv, nullptr, qp, kp, vp);

    rope_kernel<<<dim3(BTOT, 2), 256>>>();

    flash_tc_kernel<<<dim3(TSEQ / 128, NHEAD, 4), 256, FLASH2_SMEM>>>();

    // output projection + residual
    tg2_kernel<1,1><<<dim3(16, 64, 1), 256, TG2_SMEM>>>(
        ap, Wo, Wo, Wo, bo, bo, bo, x, out, out, out);
}

// round 8
// speedup vs baseline: 1.4350x; 1.4350x over previous
#include <cuda_runtime.h>
#include <math.h>
#include <stdint.h>

#define BTOT 8192      // B*T rows
#define CDIM 2048      // channels
#define TSEQ 2048      // sequence length
#define NHEAD 16
#define HDIM 128

// -------- scratch (device globals; allocation-free) --------
__device__ float g_nx [BTOT * CDIM];   // LN out: tf32-rounded, k-permuted
__device__ float g_q  [BTOT * CDIM];
__device__ float g_k  [BTOT * CDIM];
__device__ float g_v  [BTOT * CDIM];
__device__ float g_att[BTOT * CDIM];   // flash out: tf32-rounded, k-permuted
__device__ float g_wq [CDIM * CDIM];   // Wt[n][perm k], tf32
__device__ float g_wk [CDIM * CDIM];
__device__ float g_wv [CDIM * CDIM];
__device__ float g_wo [CDIM * CDIM];

__device__ __forceinline__ float to_tf32(float x) {
    uint32_t u;
    asm("cvt.rna.tf32.f32 %0, %1;" : "=r"(u) : "f"(x));
    return __uint_as_float(u);
}
__device__ __forceinline__ float4 tf32x4(float4 v) {
    return make_float4(to_tf32(v.x), to_tf32(v.y), to_tf32(v.z), to_tf32(v.w));
}
// permute k within its 32-wide chunk: chunk | 8*(k&3) + ((k&31)>>2)
__device__ __forceinline__ int permk(int k) {
    return (k & ~31) | (((k & 3) << 3) | ((k & 31) >> 2));
}
__device__ __forceinline__ void cp_async16(uint32_t dst_smem, const void* src) {
    asm volatile("cp.async.cg.shared.global [%0], [%1], 16;\n"
                 :: "r"(dst_smem), "l"(src));
}

// ===================== LayerNorm (tf32-rounded, k-permuted output) =====================
__global__ __launch_bounds__(256) void ln_kernel(const float* __restrict__ x,
                                                 const float* __restrict__ gamma,
                                                 const float* __restrict__ beta) {
    int row = blockIdx.x;
    int tid = threadIdx.x;
    const float* px = x + row * CDIM;

    float4 a0 = *(const float4*)(px + tid * 4);
    float4 a1 = *(const float4*)(px + 1024 + tid * 4);

    float s = a0.x + a0.y + a0.z + a0.w + a1.x + a1.y + a1.z + a1.w;
    float q = a0.x*a0.x + a0.y*a0.y + a0.z*a0.z + a0.w*a0.w
            + a1.x*a1.x + a1.y*a1.y + a1.z*a1.z + a1.w*a1.w;

    #pragma unroll
    for (int off = 16; off; off >>= 1) {
        s += __shfl_xor_sync(0xffffffffu, s, off);
        q += __shfl_xor_sync(0xffffffffu, q, off);
    }
    __shared__ float sh[16];
    if ((tid & 31) == 0) { sh[tid >> 5] = s; sh[8 + (tid >> 5)] = q; }
    __syncthreads();
    float ts = 0.f, tq = 0.f;
    #pragma unroll
    for (int i = 0; i < 8; i++) { ts += sh[i]; tq += sh[8 + i]; }

    float mu   = ts * (1.f / 2048.f);
    float var  = tq * (1.f / 2048.f) - mu * mu;
    float rstd = rsqrtf(var + 1e-5f);

    float4 g0 = *(const float4*)(gamma + tid * 4);
    float4 g1 = *(const float4*)(gamma + 1024 + tid * 4);
    float4 b0 = *(const float4*)(beta + tid * 4);
    float4 b1 = *(const float4*)(beta + 1024 + tid * 4);

    float* po = g_nx + (size_t)row * CDIM;
    float o[8];
    o[0] = (a0.x - mu) * rstd * g0.x + b0.x;
    o[1] = (a0.y - mu) * rstd * g0.y + b0.y;
    o[2] = (a0.z - mu) * rstd * g0.z + b0.z;
    o[3] = (a0.w - mu) * rstd * g0.w + b0.w;
    o[4] = (a1.x - mu) * rstd * g1.x + b1.x;
    o[5] = (a1.y - mu) * rstd * g1.y + b1.y;
    o[6] = (a1.z - mu) * rstd * g1.z + b1.z;
    o[7] = (a1.w - mu) * rstd * g1.w + b1.w;
    #pragma unroll
    for (int j = 0; j < 4; j++) {
        po[permk(4 * tid + j)]        = to_tf32(o[j]);
        po[permk(1024 + 4 * tid + j)] = to_tf32(o[4 + j]);
    }
}

// ===================== Weight transform: Wt[n][perm k] = rna(W[k][n]) =====================
__global__ __launch_bounds__(256) void wcvt_kernel(
    const float* __restrict__ Wq, const float* __restrict__ Wk,
    const float* __restrict__ Wv, const float* __restrict__ Wo) {
    __shared__ float tile[32][33];
    int z = blockIdx.z;
    const float* W = (z == 0) ? Wq : (z == 1) ? Wk : (z == 2) ? Wv : Wo;
    float* Wt = (z == 0) ? g_wq : (z == 1) ? g_wk : (z == 2) ? g_wv : g_wo;

    int k0 = blockIdx.x * 32, n0 = blockIdx.y * 32;
    int c = threadIdx.x & 31, r = threadIdx.x >> 5;   // r 0..7

    #pragma unroll
    for (int i = 0; i < 4; i++)
        tile[r + 8 * i][c] = W[(size_t)(k0 + r + 8 * i) * CDIM + n0 + c];
    __syncthreads();
    int po = ((c & 3) << 3) | (c >> 2);   // perm within 32-chunk
    #pragma unroll
    for (int i = 0; i < 4; i++)
        Wt[(size_t)(n0 + r + 8 * i) * CDIM + k0 + po] = to_tf32(tile[c][r + 8 * i]);
}

// ===================== tf32 GEMM v3: cp.async, permuted operands =====================
// Y = A*W + bias (+residual). A[M][2048] perm/tf32, Wt[n][2048] perm/tf32.
// 128x128 tile, BK=32, 256 thr, 8 warps (2x4), warp 64x32. 2-stage cp.async
// ping-pong, ONE barrier/iter. All fragments via conflict-free LDS.128.
#define TG3_SMEM (4 * 128 * 36 * 4)   // 73728 B (A[2]+B[2], each 128x36)

template<int MODE>   // 1: +residual
__global__ __launch_bounds__(256, 2) void tg3_kernel(
    const float* __restrict__ A,
    const float* __restrict__ B0, const float* __restrict__ B1, const float* __restrict__ B2,
    const float* __restrict__ c0, const float* __restrict__ c1, const float* __restrict__ c2,
    const float* __restrict__ R,
    float* __restrict__ Y0, float* __restrict__ Y1, float* __restrict__ Y2)
{
    const int N = CDIM;
    extern __shared__ float smp[];
    // floats: As stage s at s*4608, Bs stage s at 9216 + s*4608

    int z = blockIdx.z;
    const float* Wt   = (z == 0) ? B0 : (z == 1) ? B1 : B2;
    const float* bias = (z == 0) ? c0 : (z == 1) ? c1 : c2;
    float*       Y    = (z == 0) ? Y0 : (z == 1) ? Y1 : Y2;

    int tid = threadIdx.x, lane = tid & 31, warp = tid >> 5;
    int bm = blockIdx.y * 128, bn = blockIdx.x * 128;

    int srow = tid >> 3;            // 0..31 (+32*it)
    int sq   = (tid & 7) * 4;       // 16B chunk within 32-k

    const float* Ap = A  + (size_t)(bm + srow) * CDIM + sq;
    const float* Bp = Wt + (size_t)(bn + srow) * CDIM + sq;

    uint32_t sbase = (uint32_t)__cvta_generic_to_shared(smp);

    float c[4][4][4];
    #pragma unroll
    for (int mi = 0; mi < 4; mi++)
        #pragma unroll
        for (int ni = 0; ni < 4; ni++)
            #pragma unroll
            for (int r = 0; r < 4; r++) c[mi][ni][r] = 0.f;

    int wm = warp >> 2, wn = warp & 3;
    int mbase = wm * 64, nbase = wn * 32;
    int lq = lane >> 2, lr = lane & 3;

    // issue stage: 8 cp.async per thread (4 A rows + 4 B rows)
    auto issue = [&](int i, int s) {
        int k0 = i * 32;
        uint32_t da = sbase + (uint32_t)(s * 4608 + srow * 36 + sq) * 4;
        uint32_t db = sbase + (uint32_t)(9216 + s * 4608 + srow * 36 + sq) * 4;
        #pragma unroll
        for (int it = 0; it < 4; it++) {
            cp_async16(da + it * (32 * 36 * 4), Ap + (size_t)(it * 32) * CDIM + k0);
            cp_async16(db + it * (32 * 36 * 4), Bp + (size_t)(it * 32) * CDIM + k0);
        }
        asm volatile("cp.async.commit_group;\n" ::: "memory");
    };

    issue(0, 0);

    const int NITER = CDIM / 32;   // 64
    for (int i = 0; i < NITER; ++i) {
        int p = i & 1;
        asm volatile("cp.async.wait_group 0;\n" ::: "memory");
        __syncthreads();
        if (i + 1 < NITER) issue(i + 1, 1 - p);   // overlaps with compute below

        const float* Ab = smp + p * 4608;
        const float* Bb = smp + 9216 + p * 4608;

        #pragma unroll
        for (int pp = 0; pp < 2; pp++) {
            float4 fb[4];
            #pragma unroll
            for (int ni = 0; ni < 4; ni++)
                fb[ni] = *(const float4*)(Bb + (nbase + ni * 8 + lq) * 36 + 8 * lr + 4 * pp);
            #pragma unroll
            for (int mi = 0; mi < 4; mi++) {
                int r0 = mbase + mi * 16 + lq;
                float4 qa0 = *(const float4*)(Ab + r0 * 36 + 8 * lr + 4 * pp);
                float4 qa1 = *(const float4*)(Ab + (r0 + 8) * 36 + 8 * lr + 4 * pp);
                #pragma unroll
                for (int ni = 0; ni < 4; ni++)
                    asm volatile(
                        "mma.sync.aligned.m16n8k8.row.col.f32.tf32.tf32.f32 "
                        "{%0,%1,%2,%3}, {%4,%5,%6,%7}, {%8,%9}, {%0,%1,%2,%3};"
                        : "+f"(c[mi][ni][0]), "+f"(c[mi][ni][1]),
                          "+f"(c[mi][ni][2]), "+f"(c[mi][ni][3])
                        : "r"(__float_as_uint(qa0.x)), "r"(__float_as_uint(qa1.x)),
                          "r"(__float_as_uint(qa0.y)), "r"(__float_as_uint(qa1.y)),
                          "r"(__float_as_uint(fb[ni].x)), "r"(__float_as_uint(fb[ni].y)));
                #pragma unroll
                for (int ni = 0; ni < 4; ni++)
                    asm volatile(
                        "mma.sync.aligned.m16n8k8.row.col.f32.tf32.tf32.f32 "
                        "{%0,%1,%2,%3}, {%4,%5,%6,%7}, {%8,%9}, {%0,%1,%2,%3};"
                        : "+f"(c[mi][ni][0]), "+f"(c[mi][ni][1]),
                          "+f"(c[mi][ni][2]), "+f"(c[mi][ni][3])
                        : "r"(__float_as_uint(qa0.z)), "r"(__float_as_uint(qa1.z)),
                          "r"(__float_as_uint(qa0.w)), "r"(__float_as_uint(qa1.w)),
                          "r"(__float_as_uint(fb[ni].z)), "r"(__float_as_uint(fb[ni].w)));
            }
        }
    }

    #pragma unroll
    for (int mi = 0; mi < 4; mi++) {
        int r0 = bm + mbase + mi * 16 + lq;
        #pragma unroll
        for (int ni = 0; ni < 4; ni++) {
            int cb = bn + nbase + ni * 8 + 2 * lr;
            float bx = bias[cb], by = bias[cb + 1];
            float2 v0 = make_float2(c[mi][ni][0] + bx, c[mi][ni][1] + by);
            float2 v1 = make_float2(c[mi][ni][2] + bx, c[mi][ni][3] + by);
            if (MODE == 1) {
                float2 r0v = *(const float2*)(R + (size_t)r0 * N + cb);
                float2 r1v = *(const float2*)(R + (size_t)(r0 + 8) * N + cb);
                v0.x += r0v.x; v0.y += r0v.y;
                v1.x += r1v.x; v1.y += r1v.y;
            }
            *(float2*)(Y + (size_t)r0 * N + cb)       = v0;
            *(float2*)(Y + (size_t)(r0 + 8) * N + cb) = v1;
        }
    }
}

// ===================== RoPE (in-place on g_q / g_k) =====================
__global__ __launch_bounds__(256) void rope_kernel() {
    int row = blockIdx.x;
    float* buf = (blockIdx.y == 0) ? g_q : g_k;
    int t = row & (TSEQ - 1);

    __shared__ float cs[64], sn[64];
    if (threadIdx.x < 64) {
        float inv = powf(10000.f, -(float)threadIdx.x / 64.f);
        float ang = (float)t * inv;
        cs[threadIdx.x] = cosf(ang);
        sn[threadIdx.x] = sinf(ang);
    }
    __syncthreads();

    float* p = buf + (size_t)row * CDIM;
    for (int idx = threadIdx.x; idx < NHEAD * 64; idx += 256) {
        int h = idx >> 6, f = idx & 63;
        float a = p[h * 128 + f];
        float b = p[h * 128 + 64 + f];
        p[h * 128 + f]      = a * cs[f] - b * sn[f];
        p[h * 128 + 64 + f] = b * cs[f] + a * sn[f];
    }
}

// ===================== Flash attention (tf32 TC, causal) =====================
// Unchanged from R5 except epilogue: writes g_att tf32-rounded + k-permuted.
#define FLASH2_SMEM ((128*132 + 64*132 + 64*136 + 128*68) * 4)   // 171008 B

__global__ __launch_bounds__(256, 1) void flash_tc_kernel() {
    extern __shared__ float sm[];
    float* Qs = sm;                    // [128][132]
    float* Ks = Qs + 128 * 132;        // [64][132]
    float* Vs = Ks + 64 * 132;         // [64][136]
    float* Ps = Vs + 64 * 136;         // [128][68]

    int qb = gridDim.x - 1 - blockIdx.x;
    int h = blockIdx.y, b = blockIdx.z;
    int tid = threadIdx.x, lane = tid & 31, warp = tid >> 5;
    int lq = lane >> 2, lr = lane & 3;

    size_t base = ((size_t)b * TSEQ) * CDIM + (size_t)h * HDIM;

    #pragma unroll
    for (int it = 0; it < 16; it++) {
        int f4 = tid + it * 256;
        int r  = f4 >> 5;
        int c4 = (f4 & 31) * 4;
        float4 v = *(const float4*)(g_q + base + (size_t)(qb * 128 + r) * CDIM + c4);
        *(float4*)&Qs[r * 132 + c4] = tf32x4(v);
    }

    float m0 = -1e30f, m1 = -1e30f, l0 = 0.f, l1 = 0.f;
    float O[16][4];
    #pragma unroll
    for (int nt = 0; nt < 16; nt++)
        #pragma unroll
        for (int r = 0; r < 4; r++) O[nt][r] = 0.f;

    const float scale = 0.08838834764831845f;
    int arow = warp * 16 + lq;
    int prow0 = arow * 68, prow1 = (arow + 8) * 68;
    int grow0 = qb * 128 + arow;

    int nkb = 2 * (qb + 1);
    for (int kb = 0; kb < nkb; kb++) {
        __syncthreads();

        #pragma unroll
        for (int it = 0; it < 8; it++) {
            int f4 = tid + it * 256;
            int r  = f4 >> 5;
            int c4 = (f4 & 31) * 4;
            size_t g = base + (size_t)(kb * 64 + r) * CDIM + c4;
            *(float4*)&Ks[r * 132 + c4] = tf32x4(*(const float4*)(g_k + g));
            *(float4*)&Vs[r * 136 + c4] = tf32x4(*(const float4*)(g_v + g));
        }
        __syncthreads();

        float s[8][4];
        #pragma unroll
        for (int nt = 0; nt < 8; nt++)
            #pragma unroll
            for (int r = 0; r < 4; r++) s[nt][r] = 0.f;

        #pragma unroll
        for (int kt = 0; kt < 16; kt++) {
            int kk = kt * 8;
            uint32_t a0 = __float_as_uint(Qs[arow * 132 + kk + lr]);
            uint32_t a1 = __float_as_uint(Qs[(arow + 8) * 132 + kk + lr]);
            uint32_t a2 = __float_as_uint(Qs[arow * 132 + kk + lr + 4]);
            uint32_t a3 = __float_as_uint(Qs[(arow + 8) * 132 + kk + lr + 4]);
            #pragma unroll
            for (int nt = 0; nt < 8; nt++) {
                int nc = nt * 8 + lq;
                uint32_t b0 = __float_as_uint(Ks[nc * 132 + kk + lr]);
                uint32_t b1 = __float_as_uint(Ks[nc * 132 + kk + lr + 4]);
                asm volatile(
                    "mma.sync.aligned.m16n8k8.row.col.f32.tf32.tf32.f32 "
                    "{%0,%1,%2,%3}, {%4,%5,%6,%7}, {%8,%9}, {%0,%1,%2,%3};"
                    : "+f"(s[nt][0]), "+f"(s[nt][1]), "+f"(s[nt][2]), "+f"(s[nt][3])
                    : "r"(a0), "r"(a1), "r"(a2), "r"(a3), "r"(b0), "r"(b1));
            }
        }

        bool needmask = (kb * 64 + 63 > qb * 128 + warp * 16);
        float t0 = -1e30f, t1 = -1e30f;
        #pragma unroll
        for (int nt = 0; nt < 8; nt++) {
            if (needmask) {
                int c0 = kb * 64 + nt * 8 + 2 * lr;
                s[nt][0] = (c0     <= grow0)     ? s[nt][0] * scale : -1e30f;
                s[nt][1] = (c0 + 1 <= grow0)     ? s[nt][1] * scale : -1e30f;
                s[nt][2] = (c0     <= grow0 + 8) ? s[nt][2] * scale : -1e30f;
                s[nt][3] = (c0 + 1 <= grow0 + 8) ? s[nt][3] * scale : -1e30f;
            } else {
                s[nt][0] *= scale; s[nt][1] *= scale;
                s[nt][2] *= scale; s[nt][3] *= scale;
            }
            t0 = fmaxf(t0, fmaxf(s[nt][0], s[nt][1]));
            t1 = fmaxf(t1, fmaxf(s[nt][2], s[nt][3]));
        }
        t0 = fmaxf(t0, __shfl_xor_sync(0xffffffffu, t0, 1));
        t0 = fmaxf(t0, __shfl_xor_sync(0xffffffffu, t0, 2));
        t1 = fmaxf(t1, __shfl_xor_sync(0xffffffffu, t1, 1));
        t1 = fmaxf(t1, __shfl_xor_sync(0xffffffffu, t1, 2));

        float mn0 = fmaxf(m0, t0), mn1 = fmaxf(m1, t1);
        float al0 = __expf(m0 - mn0), al1 = __expf(m1 - mn1);
        float rs0 = 0.f, rs1 = 0.f;
        #pragma unroll
        for (int nt = 0; nt < 8; nt++) {
            float p00 = to_tf32(__expf(s[nt][0] - mn0));
            float p01 = to_tf32(__expf(s[nt][1] - mn0));
            float p10 = to_tf32(__expf(s[nt][2] - mn1));
            float p11 = to_tf32(__expf(s[nt][3] - mn1));
            rs0 += p00 + p01;
            rs1 += p10 + p11;
            *(float2*)&Ps[prow0 + nt * 8 + 2 * lr] = make_float2(p00, p01);
            *(float2*)&Ps[prow1 + nt * 8 + 2 * lr] = make_float2(p10, p11);
        }
        rs0 += __shfl_xor_sync(0xffffffffu, rs0, 1);
        rs0 += __shfl_xor_sync(0xffffffffu, rs0, 2);
        rs1 += __shfl_xor_sync(0xffffffffu, rs1, 1);
        rs1 += __shfl_xor_sync(0xffffffffu, rs1, 2);

        l0 = l0 * al0 + rs0;  l1 = l1 * al1 + rs1;
        m0 = mn0;             m1 = mn1;
        #pragma unroll
        for (int nt = 0; nt < 16; nt++) {
            O[nt][0] *= al0; O[nt][1] *= al0;
            O[nt][2] *= al1; O[nt][3] *= al1;
        }
        __syncwarp();

        #pragma unroll
        for (int kt = 0; kt < 8; kt++) {
            int kk = kt * 8;
            uint32_t a0 = __float_as_uint(Ps[prow0 + kk + lr]);
            uint32_t a1 = __float_as_uint(Ps[prow1 + kk + lr]);
            uint32_t a2 = __float_as_uint(Ps[prow0 + kk + lr + 4]);
            uint32_t a3 = __float_as_uint(Ps[prow1 + kk + lr + 4]);
            #pragma unroll
            for (int nt = 0; nt < 16; nt++) {
                int nc = nt * 8 + lq;
                uint32_t b0 = __float_as_uint(Vs[(kk + lr) * 136 + nc]);
                uint32_t b1 = __float_as_uint(Vs[(kk + lr + 4) * 136 + nc]);
                asm volatile(
                    "mma.sync.aligned.m16n8k8.row.col.f32.tf32.tf32.f32 "
                    "{%0,%1,%2,%3}, {%4,%5,%6,%7}, {%8,%9}, {%0,%1,%2,%3};"
                    : "+f"(O[nt][0]), "+f"(O[nt][1]), "+f"(O[nt][2]), "+f"(O[nt][3])
                    : "r"(a0), "r"(a1), "r"(a2), "r"(a3), "r"(b0), "r"(b1));
            }
        }
    }

    // ---- epilogue: normalize, tf32-round, write k-PERMUTED (GEMM-A layout) ----
    float inv0 = 1.f / l0, inv1 = 1.f / l1;
    size_t row0 = (size_t)b * TSEQ + grow0;
    #pragma unroll
    for (int nt = 0; nt < 16; nt++) {
        int col = h * HDIM + nt * 8 + 2 * lr;
        int p0 = permk(col), p1 = permk(col + 1);
        g_att[row0 * CDIM + p0]       = to_tf32(O[nt][0] * inv0);
        g_att[row0 * CDIM + p1]       = to_tf32(O[nt][1] * inv0);
        g_att[(row0 + 8) * CDIM + p0] = to_tf32(O[nt][2] * inv1);
        g_att[(row0 + 8) * CDIM + p1] = to_tf32(O[nt][3] * inv1);
    }
}

// ===================== launch =====================
extern "C" void kernel_launch(void* const* d_in, const int* in_sizes, int n_in,
                              void* d_out, int out_size) {
    const float* x    = (const float*)d_in[0];
    const float* ln_g = (const float*)d_in[1];
    const float* ln_b = (const float*)d_in[2];
    const float* Wq   = (const float*)d_in[3];
    const float* bq   = (const float*)d_in[4];
    const float* Wk   = (const float*)d_in[5];
    const float* bk   = (const float*)d_in[6];
    const float* Wv   = (const float*)d_in[7];
    const float* bv   = (const float*)d_in[8];
    const float* Wo   = (const float*)d_in[9];
    const float* bo   = (const float*)d_in[10];
    float* out = (float*)d_out;

    float *nx, *qp, *kp, *vp, *ap, *wq, *wk, *wv, *wo;
    cudaGetSymbolAddress((void**)&nx, g_nx);
    cudaGetSymbolAddress((void**)&qp, g_q);
    cudaGetSymbolAddress((void**)&kp, g_k);
    cudaGetSymbolAddress((void**)&vp, g_v);
    cudaGetSymbolAddress((void**)&ap, g_att);
    cudaGetSymbolAddress((void**)&wq, g_wq);
    cudaGetSymbolAddress((void**)&wk, g_wk);
    cudaGetSymbolAddress((void**)&wv, g_wv);
    cudaGetSymbolAddress((void**)&wo, g_wo);

    cudaFuncSetAttribute(flash_tc_kernel, cudaFuncAttributeMaxDynamicSharedMemorySize, FLASH2_SMEM);
    cudaFuncSetAttribute(tg3_kernel<0>, cudaFuncAttributeMaxDynamicSharedMemorySize, TG3_SMEM);
    cudaFuncSetAttribute(tg3_kernel<1>, cudaFuncAttributeMaxDynamicSharedMemorySize, TG3_SMEM);

    ln_kernel<<<BTOT, 256>>>(x, ln_g, ln_b);
    wcvt_kernel<<<dim3(64, 64, 4), 256>>>(Wq, Wk, Wv, Wo);

    // fused Q/K/V projections
    tg3_kernel<0><<<dim3(16, 64, 3), 256, TG3_SMEM>>>(
        nx, wq, wk, wv, bq, bk, bv, nullptr, qp, kp, vp);

    rope_kernel<<<dim3(BTOT, 2), 256>>>();

    flash_tc_kernel<<<dim3(TSEQ / 128, NHEAD, 4), 256, FLASH2_SMEM>>>();

    // output projection + residual
    tg3_kernel<1><<<dim3(16, 64, 1), 256, TG3_SMEM>>>(
        ap, wo, wo, wo, bo, bo, bo, x, out, out, out);
}

// round 9
// speedup vs baseline: 1.4586x; 1.0164x over previous
#include <cuda_runtime.h>
#include <math.h>
#include <stdint.h>

#define BTOT 8192      // B*T rows
#define CDIM 2048      // channels
#define TSEQ 2048      // sequence length
#define NHEAD 16
#define HDIM 128

// -------- scratch (device globals; allocation-free) --------
__device__ float g_nx [BTOT * CDIM];   // LN out: tf32-rounded, k-permuted
__device__ float g_q  [BTOT * CDIM];
__device__ float g_k  [BTOT * CDIM];
__device__ float g_v  [BTOT * CDIM];
__device__ float g_att[BTOT * CDIM];   // flash out: tf32-rounded, k-permuted
__device__ float g_wq [CDIM * CDIM];   // Wt[n][perm k], tf32
__device__ float g_wk [CDIM * CDIM];
__device__ float g_wv [CDIM * CDIM];
__device__ float g_wo [CDIM * CDIM];

__device__ __forceinline__ float to_tf32(float x) {
    uint32_t u;
    asm("cvt.rna.tf32.f32 %0, %1;" : "=r"(u) : "f"(x));
    return __uint_as_float(u);
}
__device__ __forceinline__ float4 tf32x4(float4 v) {
    return make_float4(to_tf32(v.x), to_tf32(v.y), to_tf32(v.z), to_tf32(v.w));
}
// permute k within its 32-wide chunk: chunk | 8*(k&3) + ((k&31)>>2)
__device__ __forceinline__ int permk(int k) {
    return (k & ~31) | (((k & 3) << 3) | ((k & 31) >> 2));
}
__device__ __forceinline__ void cp_async16(uint32_t dst_smem, const void* src) {
    asm volatile("cp.async.cg.shared.global [%0], [%1], 16;\n"
                 :: "r"(dst_smem), "l"(src));
}
#define CP_COMMIT() asm volatile("cp.async.commit_group;\n" ::: "memory")
#define CP_WAIT(n)  asm volatile("cp.async.wait_group %0;\n" :: "n"(n) : "memory")

// ===================== LayerNorm (tf32-rounded, k-permuted output) =====================
__global__ __launch_bounds__(256) void ln_kernel(const float* __restrict__ x,
                                                 const float* __restrict__ gamma,
                                                 const float* __restrict__ beta) {
    int row = blockIdx.x;
    int tid = threadIdx.x;
    const float* px = x + row * CDIM;

    float4 a0 = *(const float4*)(px + tid * 4);
    float4 a1 = *(const float4*)(px + 1024 + tid * 4);

    float s = a0.x + a0.y + a0.z + a0.w + a1.x + a1.y + a1.z + a1.w;
    float q = a0.x*a0.x + a0.y*a0.y + a0.z*a0.z + a0.w*a0.w
            + a1.x*a1.x + a1.y*a1.y + a1.z*a1.z + a1.w*a1.w;

    #pragma unroll
    for (int off = 16; off; off >>= 1) {
        s += __shfl_xor_sync(0xffffffffu, s, off);
        q += __shfl_xor_sync(0xffffffffu, q, off);
    }
    __shared__ float sh[16];
    if ((tid & 31) == 0) { sh[tid >> 5] = s; sh[8 + (tid >> 5)] = q; }
    __syncthreads();
    float ts = 0.f, tq = 0.f;
    #pragma unroll
    for (int i = 0; i < 8; i++) { ts += sh[i]; tq += sh[8 + i]; }

    float mu   = ts * (1.f / 2048.f);
    float var  = tq * (1.f / 2048.f) - mu * mu;
    float rstd = rsqrtf(var + 1e-5f);

    float4 g0 = *(const float4*)(gamma + tid * 4);
    float4 g1 = *(const float4*)(gamma + 1024 + tid * 4);
    float4 b0 = *(const float4*)(beta + tid * 4);
    float4 b1 = *(const float4*)(beta + 1024 + tid * 4);

    float* po = g_nx + (size_t)row * CDIM;
    float o[8];
    o[0] = (a0.x - mu) * rstd * g0.x + b0.x;
    o[1] = (a0.y - mu) * rstd * g0.y + b0.y;
    o[2] = (a0.z - mu) * rstd * g0.z + b0.z;
    o[3] = (a0.w - mu) * rstd * g0.w + b0.w;
    o[4] = (a1.x - mu) * rstd * g1.x + b1.x;
    o[5] = (a1.y - mu) * rstd * g1.y + b1.y;
    o[6] = (a1.z - mu) * rstd * g1.z + b1.z;
    o[7] = (a1.w - mu) * rstd * g1.w + b1.w;
    #pragma unroll
    for (int j = 0; j < 4; j++) {
        po[permk(4 * tid + j)]        = to_tf32(o[j]);
        po[permk(1024 + 4 * tid + j)] = to_tf32(o[4 + j]);
    }
}

// ===================== Weight transform: Wt[n][perm k] = rna(W[k][n]) =====================
__global__ __launch_bounds__(256) void wcvt_kernel(
    const float* __restrict__ Wq, const float* __restrict__ Wk,
    const float* __restrict__ Wv, const float* __restrict__ Wo) {
    __shared__ float tile[32][33];
    int z = blockIdx.z;
    const float* W = (z == 0) ? Wq : (z == 1) ? Wk : (z == 2) ? Wv : Wo;
    float* Wt = (z == 0) ? g_wq : (z == 1) ? g_wk : (z == 2) ? g_wv : g_wo;

    int k0 = blockIdx.x * 32, n0 = blockIdx.y * 32;
    int c = threadIdx.x & 31, r = threadIdx.x >> 5;   // r 0..7

    #pragma unroll
    for (int i = 0; i < 4; i++)
        tile[r + 8 * i][c] = W[(size_t)(k0 + r + 8 * i) * CDIM + n0 + c];
    __syncthreads();
    int po = ((c & 3) << 3) | (c >> 2);   // perm within 32-chunk
    #pragma unroll
    for (int i = 0; i < 4; i++)
        Wt[(size_t)(n0 + r + 8 * i) * CDIM + k0 + po] = to_tf32(tile[c][r + 8 * i]);
}

// ===================== tf32 GEMM v3.1: 3-stage cp.async ring =====================
// Y = A*W + bias (+residual). A[M][2048] perm/tf32, Wt[n][2048] perm/tf32.
// 128x128 tile, BK=32, 256 thr, 8 warps (2x4), warp 64x32. THREE-stage cp.async
// ring with wait_group 1 (each copy gets ~2 iters of slack). One barrier/iter.
#define TG3_SMEM (6 * 4608 * 4)   // 110592 B : A stages 0..2, B stages 0..2

template<int MODE>   // 0: +bias, round output tf32 ; 1: +bias+residual, fp32 out
__global__ __launch_bounds__(256, 2) void tg3_kernel(
    const float* __restrict__ A,
    const float* __restrict__ B0, const float* __restrict__ B1, const float* __restrict__ B2,
    const float* __restrict__ c0, const float* __restrict__ c1, const float* __restrict__ c2,
    const float* __restrict__ R,
    float* __restrict__ Y0, float* __restrict__ Y1, float* __restrict__ Y2)
{
    const int N = CDIM;
    extern __shared__ float smp[];
    // A stage s at s*4608 floats; B stage s at 13824 + s*4608

    int z = blockIdx.z;
    const float* Wt   = (z == 0) ? B0 : (z == 1) ? B1 : B2;
    const float* bias = (z == 0) ? c0 : (z == 1) ? c1 : c2;
    float*       Y    = (z == 0) ? Y0 : (z == 1) ? Y1 : Y2;

    int tid = threadIdx.x, lane = tid & 31, warp = tid >> 5;
    int bm = blockIdx.y * 128, bn = blockIdx.x * 128;

    int srow = tid >> 3;            // 0..31 (+32*it)
    int sq   = (tid & 7) * 4;       // 16B chunk within 32-k

    const float* Ap = A  + (size_t)(bm + srow) * CDIM + sq;
    const float* Bp = Wt + (size_t)(bn + srow) * CDIM + sq;

    uint32_t sbase = (uint32_t)__cvta_generic_to_shared(smp);

    float c[4][4][4];
    #pragma unroll
    for (int mi = 0; mi < 4; mi++)
        #pragma unroll
        for (int ni = 0; ni < 4; ni++)
            #pragma unroll
            for (int r = 0; r < 4; r++) c[mi][ni][r] = 0.f;

    int wm = warp >> 2, wn = warp & 3;
    int mbase = wm * 64, nbase = wn * 32;
    int lq = lane >> 2, lr = lane & 3;

    auto issue = [&](int i, int s) {
        int k0 = i * 32;
        uint32_t da = sbase + (uint32_t)(s * 4608 + srow * 36 + sq) * 4;
        uint32_t db = sbase + (uint32_t)(13824 + s * 4608 + srow * 36 + sq) * 4;
        #pragma unroll
        for (int it = 0; it < 4; it++) {
            cp_async16(da + it * (32 * 36 * 4), Ap + (size_t)(it * 32) * CDIM + k0);
            cp_async16(db + it * (32 * 36 * 4), Bp + (size_t)(it * 32) * CDIM + k0);
        }
        CP_COMMIT();
    };

    issue(0, 0);
    issue(1, 1);

    const int NITER = CDIM / 32;   // 64
    for (int i = 0; i < NITER; ++i) {
        int s = i - (i / 3) * 3;   // i % 3
        if (i == NITER - 1) { CP_WAIT(0); } else { CP_WAIT(1); }
        __syncthreads();
        if (i + 2 < NITER) issue(i + 2, (i + 2) % 3);

        const float* Ab = smp + s * 4608;
        const float* Bb = smp + 13824 + s * 4608;

        #pragma unroll
        for (int pp = 0; pp < 2; pp++) {
            float4 fb[4];
            #pragma unroll
            for (int ni = 0; ni < 4; ni++)
                fb[ni] = *(const float4*)(Bb + (nbase + ni * 8 + lq) * 36 + 8 * lr + 4 * pp);
            #pragma unroll
            for (int mi = 0; mi < 4; mi++) {
                int r0 = mbase + mi * 16 + lq;
                float4 qa0 = *(const float4*)(Ab + r0 * 36 + 8 * lr + 4 * pp);
                float4 qa1 = *(const float4*)(Ab + (r0 + 8) * 36 + 8 * lr + 4 * pp);
                #pragma unroll
                for (int ni = 0; ni < 4; ni++)
                    asm volatile(
                        "mma.sync.aligned.m16n8k8.row.col.f32.tf32.tf32.f32 "
                        "{%0,%1,%2,%3}, {%4,%5,%6,%7}, {%8,%9}, {%0,%1,%2,%3};"
                        : "+f"(c[mi][ni][0]), "+f"(c[mi][ni][1]),
                          "+f"(c[mi][ni][2]), "+f"(c[mi][ni][3])
                        : "r"(__float_as_uint(qa0.x)), "r"(__float_as_uint(qa1.x)),
                          "r"(__float_as_uint(qa0.y)), "r"(__float_as_uint(qa1.y)),
                          "r"(__float_as_uint(fb[ni].x)), "r"(__float_as_uint(fb[ni].y)));
                #pragma unroll
                for (int ni = 0; ni < 4; ni++)
                    asm volatile(
                        "mma.sync.aligned.m16n8k8.row.col.f32.tf32.tf32.f32 "
                        "{%0,%1,%2,%3}, {%4,%5,%6,%7}, {%8,%9}, {%0,%1,%2,%3};"
                        : "+f"(c[mi][ni][0]), "+f"(c[mi][ni][1]),
                          "+f"(c[mi][ni][2]), "+f"(c[mi][ni][3])
                        : "r"(__float_as_uint(qa0.z)), "r"(__float_as_uint(qa1.z)),
                          "r"(__float_as_uint(qa0.w)), "r"(__float_as_uint(qa1.w)),
                          "r"(__float_as_uint(fb[ni].z)), "r"(__float_as_uint(fb[ni].w)));
            }
        }
    }

    #pragma unroll
    for (int mi = 0; mi < 4; mi++) {
        int r0 = bm + mbase + mi * 16 + lq;
        #pragma unroll
        for (int ni = 0; ni < 4; ni++) {
            int cb = bn + nbase + ni * 8 + 2 * lr;
            float bx = bias[cb], by = bias[cb + 1];
            float2 v0 = make_float2(c[mi][ni][0] + bx, c[mi][ni][1] + by);
            float2 v1 = make_float2(c[mi][ni][2] + bx, c[mi][ni][3] + by);
            if (MODE == 1) {
                float2 r0v = *(const float2*)(R + (size_t)r0 * N + cb);
                float2 r1v = *(const float2*)(R + (size_t)(r0 + 8) * N + cb);
                v0.x += r0v.x; v0.y += r0v.y;
                v1.x += r1v.x; v1.y += r1v.y;
            } else {
                // q/k/v feed tf32 MMAs downstream via raw cp.async: pre-round.
                v0.x = to_tf32(v0.x); v0.y = to_tf32(v0.y);
                v1.x = to_tf32(v1.x); v1.y = to_tf32(v1.y);
            }
            *(float2*)(Y + (size_t)r0 * N + cb)       = v0;
            *(float2*)(Y + (size_t)(r0 + 8) * N + cb) = v1;
        }
    }
}

// ===================== RoPE (in-place, writes tf32-rounded) =====================
__global__ __launch_bounds__(256) void rope_kernel() {
    int row = blockIdx.x;
    float* buf = (blockIdx.y == 0) ? g_q : g_k;
    int t = row & (TSEQ - 1);

    __shared__ float cs[64], sn[64];
    if (threadIdx.x < 64) {
        float inv = powf(10000.f, -(float)threadIdx.x / 64.f);
        float ang = (float)t * inv;
        cs[threadIdx.x] = cosf(ang);
        sn[threadIdx.x] = sinf(ang);
    }
    __syncthreads();

    float* p = buf + (size_t)row * CDIM;
    for (int idx = threadIdx.x; idx < NHEAD * 64; idx += 256) {
        int h = idx >> 6, f = idx & 63;
        float a = p[h * 128 + f];
        float b = p[h * 128 + 64 + f];
        p[h * 128 + f]      = to_tf32(a * cs[f] - b * sn[f]);
        p[h * 128 + 64 + f] = to_tf32(b * cs[f] + a * sn[f]);
    }
}

// ===================== Flash attention v3: cp.async K double-buffer + early V ====
// grid: (T/128 [reversed], H, B); 256 thr = 8 warps; each warp owns 16 q-rows.
// K(kb+1) and V(kb) stream via cp.async while S-mma/softmax run. K,V arrive
// pre-rounded to tf32 (rope / tg3 epilogue), so raw byte copies are exact.
#define FLASH3_SMEM (51200 * 4)   // Qs 16896 + K0/K1 8448*2 + Vs 8704 + Ps 8704

__global__ __launch_bounds__(256, 1) void flash_tc_kernel() {
    extern __shared__ float sm[];
    float* Qs = sm;                    // [128][132]
    float* K0 = sm + 16896;            // [64][132]
    float* K1 = sm + 25344;            // [64][132]
    float* Vs = sm + 33792;            // [64][136]
    float* Ps = sm + 42496;            // [128][68]
    uint32_t sb  = (uint32_t)__cvta_generic_to_shared(sm);
    uint32_t k0a = sb + 16896u * 4, k1a = sb + 25344u * 4, va = sb + 33792u * 4;

    int qb = gridDim.x - 1 - blockIdx.x;
    int h = blockIdx.y, b = blockIdx.z;
    int tid = threadIdx.x, lane = tid & 31, warp = tid >> 5;
    int lq = lane >> 2, lr = lane & 3;

    size_t base = ((size_t)b * TSEQ) * CDIM + (size_t)h * HDIM;

    // Q tile (pre-rounded by rope; cvt kept for safety, idempotent)
    #pragma unroll
    for (int it = 0; it < 16; it++) {
        int f4 = tid + it * 256;
        int r  = f4 >> 5;
        int c4 = (f4 & 31) * 4;
        float4 v = *(const float4*)(g_q + base + (size_t)(qb * 128 + r) * CDIM + c4);
        *(float4*)&Qs[r * 132 + c4] = tf32x4(v);
    }

    float m0 = -1e30f, m1 = -1e30f, l0 = 0.f, l1 = 0.f;
    float O[16][4];
    #pragma unroll
    for (int nt = 0; nt < 16; nt++)
        #pragma unroll
        for (int r = 0; r < 4; r++) O[nt][r] = 0.f;

    const float scale = 0.08838834764831845f;
    int arow = warp * 16 + lq;
    int prow0 = arow * 68, prow1 = (arow + 8) * 68;
    int grow0 = qb * 128 + arow;
    int nkb = 2 * (qb + 1);

    // prologue: K(0) -> K0
    #pragma unroll
    for (int it = 0; it < 8; it++) {
        int f4 = tid + it * 256;
        int r  = f4 >> 5;
        int c4 = (f4 & 31) * 4;
        cp_async16(k0a + (uint32_t)(r * 132 + c4) * 4,
                   g_k + base + (size_t)r * CDIM + c4);
    }
    CP_COMMIT();

    for (int kb = 0; kb < nkb; kb++) {
        __syncthreads();   // (A) PV(kb-1) done: Vs + K-target buffer free

        // stream V(kb)
        #pragma unroll
        for (int it = 0; it < 8; it++) {
            int f4 = tid + it * 256;
            int r  = f4 >> 5;
            int c4 = (f4 & 31) * 4;
            cp_async16(va + (uint32_t)(r * 136 + c4) * 4,
                       g_v + base + (size_t)(kb * 64 + r) * CDIM + c4);
        }
        CP_COMMIT();

        bool more = (kb + 1 < nkb);
        if (more) {   // stream K(kb+1)
            uint32_t ka = ((kb + 1) & 1) ? k1a : k0a;
            #pragma unroll
            for (int it = 0; it < 8; it++) {
                int f4 = tid + it * 256;
                int r  = f4 >> 5;
                int c4 = (f4 & 31) * 4;
                cp_async16(ka + (uint32_t)(r * 132 + c4) * 4,
                           g_k + base + (size_t)((kb + 1) * 64 + r) * CDIM + c4);
            }
            CP_COMMIT();
        }

        if (more) { CP_WAIT(2); } else { CP_WAIT(1); }   // K(kb) ready
        __syncthreads();   // (B)

        const float* Kc = (kb & 1) ? K1 : K0;

        // ---- S = Q K^T : warp computes 16x64 ----
        float s[8][4];
        #pragma unroll
        for (int nt = 0; nt < 8; nt++)
            #pragma unroll
            for (int r = 0; r < 4; r++) s[nt][r] = 0.f;

        #pragma unroll
        for (int kt = 0; kt < 16; kt++) {
            int kk = kt * 8;
            uint32_t a0 = __float_as_uint(Qs[arow * 132 + kk + lr]);
            uint32_t a1 = __float_as_uint(Qs[(arow + 8) * 132 + kk + lr]);
            uint32_t a2 = __float_as_uint(Qs[arow * 132 + kk + lr + 4]);
            uint32_t a3 = __float_as_uint(Qs[(arow + 8) * 132 + kk + lr + 4]);
            #pragma unroll
            for (int nt = 0; nt < 8; nt++) {
                int nc = nt * 8 + lq;
                uint32_t b0 = __float_as_uint(Kc[nc * 132 + kk + lr]);
                uint32_t b1 = __float_as_uint(Kc[nc * 132 + kk + lr + 4]);
                asm volatile(
                    "mma.sync.aligned.m16n8k8.row.col.f32.tf32.tf32.f32 "
                    "{%0,%1,%2,%3}, {%4,%5,%6,%7}, {%8,%9}, {%0,%1,%2,%3};"
                    : "+f"(s[nt][0]), "+f"(s[nt][1]), "+f"(s[nt][2]), "+f"(s[nt][3])
                    : "r"(a0), "r"(a1), "r"(a2), "r"(a3), "r"(b0), "r"(b1));
            }
        }

        // ---- scale + causal mask + online softmax ----
        bool needmask = (kb * 64 + 63 > qb * 128 + warp * 16);
        float t0 = -1e30f, t1 = -1e30f;
        #pragma unroll
        for (int nt = 0; nt < 8; nt++) {
            if (needmask) {
                int c0 = kb * 64 + nt * 8 + 2 * lr;
                s[nt][0] = (c0     <= grow0)     ? s[nt][0] * scale : -1e30f;
                s[nt][1] = (c0 + 1 <= grow0)     ? s[nt][1] * scale : -1e30f;
                s[nt][2] = (c0     <= grow0 + 8) ? s[nt][2] * scale : -1e30f;
                s[nt][3] = (c0 + 1 <= grow0 + 8) ? s[nt][3] * scale : -1e30f;
            } else {
                s[nt][0] *= scale; s[nt][1] *= scale;
                s[nt][2] *= scale; s[nt][3] *= scale;
            }
            t0 = fmaxf(t0, fmaxf(s[nt][0], s[nt][1]));
            t1 = fmaxf(t1, fmaxf(s[nt][2], s[nt][3]));
        }
        t0 = fmaxf(t0, __shfl_xor_sync(0xffffffffu, t0, 1));
        t0 = fmaxf(t0, __shfl_xor_sync(0xffffffffu, t0, 2));
        t1 = fmaxf(t1, __shfl_xor_sync(0xffffffffu, t1, 1));
        t1 = fmaxf(t1, __shfl_xor_sync(0xffffffffu, t1, 2));

        float mn0 = fmaxf(m0, t0), mn1 = fmaxf(m1, t1);
        float al0 = __expf(m0 - mn0), al1 = __expf(m1 - mn1);
        float rs0 = 0.f, rs1 = 0.f;
        #pragma unroll
        for (int nt = 0; nt < 8; nt++) {
            float p00 = to_tf32(__expf(s[nt][0] - mn0));
            float p01 = to_tf32(__expf(s[nt][1] - mn0));
            float p10 = to_tf32(__expf(s[nt][2] - mn1));
            float p11 = to_tf32(__expf(s[nt][3] - mn1));
            rs0 += p00 + p01;
            rs1 += p10 + p11;
            *(float2*)&Ps[prow0 + nt * 8 + 2 * lr] = make_float2(p00, p01);
            *(float2*)&Ps[prow1 + nt * 8 + 2 * lr] = make_float2(p10, p11);
        }
        rs0 += __shfl_xor_sync(0xffffffffu, rs0, 1);
        rs0 += __shfl_xor_sync(0xffffffffu, rs0, 2);
        rs1 += __shfl_xor_sync(0xffffffffu, rs1, 1);
        rs1 += __shfl_xor_sync(0xffffffffu, rs1, 2);

        l0 = l0 * al0 + rs0;  l1 = l1 * al1 + rs1;
        m0 = mn0;             m1 = mn1;
        #pragma unroll
        for (int nt = 0; nt < 16; nt++) {
            O[nt][0] *= al0; O[nt][1] *= al0;
            O[nt][2] *= al1; O[nt][3] *= al1;
        }
        __syncwarp();

        if (more) { CP_WAIT(1); } else { CP_WAIT(0); }   // V(kb) ready
        __syncthreads();   // (C)

        // ---- O += P V : warp computes 16x128 ----
        #pragma unroll
        for (int kt = 0; kt < 8; kt++) {
            int kk = kt * 8;
            uint32_t a0 = __float_as_uint(Ps[prow0 + kk + lr]);
            uint32_t a1 = __float_as_uint(Ps[prow1 + kk + lr]);
            uint32_t a2 = __float_as_uint(Ps[prow0 + kk + lr + 4]);
            uint32_t a3 = __float_as_uint(Ps[prow1 + kk + lr + 4]);
            #pragma unroll
            for (int nt = 0; nt < 16; nt++) {
                int nc = nt * 8 + lq;
                uint32_t b0 = __float_as_uint(Vs[(kk + lr) * 136 + nc]);
                uint32_t b1 = __float_as_uint(Vs[(kk + lr + 4) * 136 + nc]);
                asm volatile(
                    "mma.sync.aligned.m16n8k8.row.col.f32.tf32.tf32.f32 "
                    "{%0,%1,%2,%3}, {%4,%5,%6,%7}, {%8,%9}, {%0,%1,%2,%3};"
                    : "+f"(O[nt][0]), "+f"(O[nt][1]), "+f"(O[nt][2]), "+f"(O[nt][3])
                    : "r"(a0), "r"(a1), "r"(a2), "r"(a3), "r"(b0), "r"(b1));
            }
        }
    }

    // ---- epilogue: normalize, tf32-round, write k-PERMUTED (GEMM-A layout) ----
    float inv0 = 1.f / l0, inv1 = 1.f / l1;
    size_t row0 = (size_t)b * TSEQ + grow0;
    #pragma unroll
    for (int nt = 0; nt < 16; nt++) {
        int col = h * HDIM + nt * 8 + 2 * lr;
        int p0 = permk(col), p1 = permk(col + 1);
        g_att[row0 * CDIM + p0]       = to_tf32(O[nt][0] * inv0);
        g_att[row0 * CDIM + p1]       = to_tf32(O[nt][1] * inv0);
        g_att[(row0 + 8) * CDIM + p0] = to_tf32(O[nt][2] * inv1);
        g_att[(row0 + 8) * CDIM + p1] = to_tf32(O[nt][3] * inv1);
    }
}

// ===================== launch =====================
extern "C" void kernel_launch(void* const* d_in, const int* in_sizes, int n_in,
                              void* d_out, int out_size) {
    const float* x    = (const float*)d_in[0];
    const float* ln_g = (const float*)d_in[1];
    const float* ln_b = (const float*)d_in[2];
    const float* Wq   = (const float*)d_in[3];
    const float* bq   = (const float*)d_in[4];
    const float* Wk   = (const float*)d_in[5];
    const float* bk   = (const float*)d_in[6];
    const float* Wv   = (const float*)d_in[7];
    const float* bv   = (const float*)d_in[8];
    const float* Wo   = (const float*)d_in[9];
    const float* bo   = (const float*)d_in[10];
    float* out = (float*)d_out;

    float *nx, *qp, *kp, *vp, *ap, *wq, *wk, *wv, *wo;
    cudaGetSymbolAddress((void**)&nx, g_nx);
    cudaGetSymbolAddress((void**)&qp, g_q);
    cudaGetSymbolAddress((void**)&kp, g_k);
    cudaGetSymbolAddress((void**)&vp, g_v);
    cudaGetSymbolAddress((void**)&ap, g_att);
    cudaGetSymbolAddress((void**)&wq, g_wq);
    cudaGetSymbolAddress((void**)&wk, g_wk);
    cudaGetSymbolAddress((void**)&wv, g_wv);
    cudaGetSymbolAddress((void**)&wo, g_wo);

    cudaFuncSetAttribute(flash_tc_kernel, cudaFuncAttributeMaxDynamicSharedMemorySize, FLASH3_SMEM);
    cudaFuncSetAttribute(tg3_kernel<0>, cudaFuncAttributeMaxDynamicSharedMemorySize, TG3_SMEM);
    cudaFuncSetAttribute(tg3_kernel<1>, cudaFuncAttributeMaxDynamicSharedMemorySize, TG3_SMEM);

    ln_kernel<<<BTOT, 256>>>(x, ln_g, ln_b);
    wcvt_kernel<<<dim3(64, 64, 4), 256>>>(Wq, Wk, Wv, Wo);

    // fused Q/K/V projections
    tg3_kernel<0><<<dim3(16, 64, 3), 256, TG3_SMEM>>>(
        nx, wq, wk, wv, bq, bk, bv, nullptr, qp, kp, vp);

    rope_kernel<<<dim3(BTOT, 2), 256>>>();

    flash_tc_kernel<<<dim3(TSEQ / 128, NHEAD, 4), 256, FLASH3_SMEM>>>();

    // output projection + residual
    tg3_kernel<1><<<dim3(16, 64, 1), 256, TG3_SMEM>>>(
        ap, wo, wo, wo, bo, bo, bo, x, out, out, out);
}